// round 13
// baseline (speedup 1.0000x reference)
#include <cuda_runtime.h>
#include <math.h>

#define NS 8192
#define NT 8192
#define NC 91
#define NO_OBJ 90

#define SXB 32                  // student x bins
#define TXB 64                  // teacher x bins
#define YB  64                  // y bins (both)
#define NSCELL (SXB * YB)       // 2048
#define NTCELL (TXB * YB)       // 4096
#define SBLK (NS / 256)         // 32 student blocks of 256
#define ROW_BLOCKS (NS / 32)    // 256 one-warp blocks

// ---------------- scratch (static __device__, no allocations) ----------------
__device__ unsigned int g_cur[NSCELL + NTCELL];
__device__ int g_sstart[NSCELL + 1];
__device__ int g_tstart[NTCELL + 1];
__device__ float4 g_sbox[NS];          // sorted (x1,y1,x2+1,y2+1)
__device__ int    g_sidx[NS];
__device__ float4 g_tbox[NT];
__device__ float2 g_tmeta[NT];         // (area, idx_bits)
__device__ unsigned long long g_key[NS];   // per ORIGINAL student packed best
__device__ float g_bel[NS];            // precomputed -log ps[s][NO_OBJ]
__device__ float g_bpart[ROW_BLOCKS * 3];
__device__ unsigned int g_count = 0;

__device__ __forceinline__ int bin_sx(float x) {
    return min(max((int)(x * (SXB / 1000.0f)), 0), SXB - 1);
}
__device__ __forceinline__ int bin_tx(float x) {
    return min(max((int)(x * (TXB / 1000.0f)), 0), TXB - 1);
}
__device__ __forceinline__ int bin_y(float y) {
    return min(max((int)(y * (YB / 1000.0f)), 0), YB - 1);
}

__device__ __forceinline__ unsigned int wscan(unsigned int x, int lane) {
#pragma unroll
    for (int o = 1; o < 32; o <<= 1) {
        unsigned int y = __shfl_up_sync(0xffffffffu, x, o);
        if (lane >= o) x += y;
    }
    return x;
}

// Conservative integer prune, units of 1/32 px, +-1 slack for float-bin rounding.
__device__ __forceinline__ void block_xbounds(int sb, int& BXLO, int& BXHI) {
    int b0 = bin_sx(g_sbox[sb * 256].x);
    int b1 = bin_sx(g_sbox[sb * 256 + 255].x);
    BXLO = b0 * 1000 - 1;                  // 31.25px * 32 = 1000
    BXHI = (b1 + 1) * 1000 + 3361;         // + maxExtent 105px*32 + slack
}
__device__ __forceinline__ bool tx_live(int tx, int BXLO, int BXHI) {
    int TXLO = tx * 500 - 1;               // 15.625px * 32 = 500
    int TXHI = (tx + 1) * 500 + 3361;
    return !(TXLO >= BXHI || TXHI <= BXLO);
}

// ---------------- kernel 1: fused hist(smem)+scan (2 independent blocks) ----
__global__ void __launch_bounds__(1024) scan_kernel(const float* __restrict__ bs,
                                                    const float* __restrict__ bt) {
    __shared__ unsigned int ws[32];
    int tid = threadIdx.x, lane = tid & 31, w = tid >> 5;

    if (blockIdx.x == 0) {
        // ----- students: smem histogram + scan + g_key reset -----
        __shared__ unsigned int sh[NSCELL];
        sh[2 * tid] = 0; sh[2 * tid + 1] = 0;
#pragma unroll
        for (int k = 0; k < 8; k++) g_key[tid + k * 1024] = 0ull;  // replay reset
        __syncthreads();
#pragma unroll
        for (int k = 0; k < 8; k++) {
            float4 r = ((const float4*)bs)[tid + k * 1024];
            atomicAdd(&sh[bin_sx(r.x) * YB + bin_y(r.y)], 1u);
        }
        __syncthreads();
        unsigned int v0 = sh[2 * tid], v1 = sh[2 * tid + 1];
        unsigned int tot = v0 + v1;
        unsigned int x = wscan(tot, lane);
        if (lane == 31) ws[w] = x;
        __syncthreads();
        if (w == 0) { unsigned int a = ws[lane]; unsigned int sa = wscan(a, lane); ws[lane] = sa - a; }
        __syncthreads();
        unsigned int base = x - tot + ws[w];
        g_sstart[2 * tid] = (int)base;
        g_sstart[2 * tid + 1] = (int)(base + v0);
        g_cur[2 * tid] = base;
        g_cur[2 * tid + 1] = base + v0;
        if (tid == 0) g_sstart[NSCELL] = NS;
    } else {
        // ----- teachers: smem histogram + scan -----
        __shared__ unsigned int sh[NTCELL];
#pragma unroll
        for (int k = 0; k < 4; k++) sh[4 * tid + k] = 0;
        __syncthreads();
#pragma unroll
        for (int k = 0; k < 8; k++) {
            float4 r = ((const float4*)bt)[tid + k * 1024];
            atomicAdd(&sh[bin_tx(r.x) * YB + bin_y(r.y)], 1u);
        }
        __syncthreads();
        unsigned int v[4]; unsigned int tot = 0;
#pragma unroll
        for (int k = 0; k < 4; k++) { v[k] = sh[4 * tid + k]; tot += v[k]; }
        unsigned int x = wscan(tot, lane);
        if (lane == 31) ws[w] = x;
        __syncthreads();
        if (w == 0) { unsigned int a = ws[lane]; unsigned int sa = wscan(a, lane); ws[lane] = sa - a; }
        __syncthreads();
        unsigned int base = x - tot + ws[w];
#pragma unroll
        for (int k = 0; k < 4; k++) {
            g_tstart[4 * tid + k] = (int)base;
            g_cur[NSCELL + 4 * tid + k] = base;
            base += v[k];
        }
        if (tid == 0) g_tstart[NTCELL] = NT;
    }
}

// ---------------- kernel 2: scatter + precompute below-term ----------------
__global__ void __launch_bounds__(256) scatter_kernel(const float* __restrict__ bs,
                                                      const float* __restrict__ bt,
                                                      const float* __restrict__ ps) {
    int i = blockIdx.x * 256 + threadIdx.x;
    g_bel[i] = -__logf(ps[(size_t)i * NC + NO_OBJ]);   // hides under atomic latency
    {
        float4 r = ((const float4*)bs)[i];
        unsigned int pos = atomicAdd(&g_cur[bin_sx(r.x) * YB + bin_y(r.y)], 1u);
        g_sbox[pos] = make_float4(r.x, r.y, r.z + 1.0f, r.w + 1.0f);
        g_sidx[pos] = i;
    }
    {
        float4 r = ((const float4*)bt)[i];
        unsigned int pos = atomicAdd(&g_cur[NSCELL + bin_tx(r.x) * YB + bin_y(r.y)], 1u);
        float x2 = r.z + 1.0f, y2 = r.w + 1.0f;
        g_tbox[pos] = make_float4(r.x, r.y, x2, y2);
        g_tmeta[pos] = make_float2((x2 - r.x) * (y2 - r.y), __int_as_float(i));
    }
}

#define IOU_STEP(J, U, D, I) {                                        \
    float4 t = __ldg(&g_tbox[J]); float2 m = __ldg(&g_tmeta[J]);      \
    float w_ = fminf(sbx.z, t.z) - fmaxf(sbx.x, t.x);                 \
    float h_ = fminf(sbx.w, t.w) - fmaxf(sbx.y, t.y);                 \
    w_ = fmaxf(w_, 0.0f);          /* h unclamped: u<=0 never wins */ \
    float u_ = w_ * h_;                                               \
    float dd_ = sA + m.x;                                             \
    if (u_ * (D) > (U) * dd_) { U = u_; D = dd_; I = __float_as_int(m.y); } }

#define CHAIN_MERGE(UB, DB, IB, UO, DO_, IO) {                        \
    float l_ = (UO) * (DB), r_ = (UB) * (DO_);                        \
    if (l_ > r_ || (l_ == r_ && (IO) < (IB))) { UB = UO; DB = DO_; IB = IO; } }

// ---------------- kernel 3: pruned, y-windowed IoU argmax -> atomicMax ------
__global__ void __launch_bounds__(256) iou_kernel() {
    int tid = threadIdx.x;
    int sb = blockIdx.x, tx = blockIdx.y;

    int BXLO, BXHI;
    block_xbounds(sb, BXLO, BXHI);
    if (!tx_live(tx, BXLO, BXHI)) return;     // block-uniform early exit, ~10 instr

    int p = sb * 256 + tid;
    float4 sbx = g_sbox[p];
    float sA = (sbx.z - sbx.x) * (sbx.w - sbx.y);

    // warp y-window (students y-sorted within block -> tight per warp)
    float wy0 = sbx.y, wy1 = sbx.w;
#pragma unroll
    for (int o = 16; o > 0; o >>= 1) {
        wy0 = fminf(wy0, __shfl_xor_sync(0xffffffffu, wy0, o));
        wy1 = fmaxf(wy1, __shfl_xor_sync(0xffffffffu, wy1, o));
    }
    int ylo = bin_y(wy0 - 105.0f);
    int yhi = bin_y(wy1);
    int jlo = g_tstart[(tx << 6) + ylo];       // exact contiguous window from
    int jhi = g_tstart[(tx << 6) + yhi + 1];   // bin table (order-independent)

    float u0 = 0.0f, d0 = 1.0f; int i0 = 0x7fffffff;
    float u1 = 0.0f, d1 = 1.0f; int i1 = 0x7fffffff;
    float u2 = 0.0f, d2 = 1.0f; int i2 = 0x7fffffff;
    float u3 = 0.0f, d3 = 1.0f; int i3 = 0x7fffffff;

    // warp-uniform addresses -> broadcast LDG; 4 chains hide load+select latency
    int j = jlo;
    for (; j + 3 < jhi; j += 4) {
        IOU_STEP(j,     u0, d0, i0);
        IOU_STEP(j + 1, u1, d1, i1);
        IOU_STEP(j + 2, u2, d2, i2);
        IOU_STEP(j + 3, u3, d3, i3);
    }
    for (; j < jhi; j++) IOU_STEP(j, u0, d0, i0);

    CHAIN_MERGE(u0, d0, i0, u1, d1, i1);
    CHAIN_MERGE(u2, d2, i2, u3, d3, i3);
    CHAIN_MERGE(u0, d0, i0, u2, d2, i2);

    if (u0 > 0.0f) {
        // ratio = u/d in [0, 0.5]; bits monotone. Low word: larger = smaller idx.
        float ratio = u0 / d0;
        unsigned long long key =
            ((unsigned long long)__float_as_uint(ratio) << 32) |
            (unsigned int)(0x7fffffff - i0);
        atomicMax(&g_key[g_sidx[p]], key);     // order-independent -> deterministic
    }
}

// ---------------- kernel 4: one warp / 32 students, ballot-scheduled KL -----
__global__ void __launch_bounds__(32) row_kernel(const float* __restrict__ ps,
                                                 const float* __restrict__ pt,
                                                 float* __restrict__ out) {
    int lane = threadIdx.x;
    int s = blockIdx.x * 32 + lane;            // ORIGINAL student id

    unsigned long long key = g_key[s];         // coalesced 256B
    float ratio = __uint_as_float((unsigned int)(key >> 32));
    int idx = 0x7fffffff - (int)(key & 0xffffffffu);

    float iou = ratio / (1.0f - ratio);        // == u/(d-u), ratio <= 0.5
    bool above = iou > 0.75f;

    float b_val = above ? 0.0f : g_bel[s];     // coalesced (precomputed)
    float f_val = above ? 1.0f : 0.0f;

    // cooperative KL for each above lane, in fixed bit order (deterministic)
    float a_sum = 0.0f;
    unsigned int mask = __ballot_sync(0xffffffffu, above);
    while (mask) {
        int b = __ffs(mask) - 1;
        mask &= mask - 1;
        int s_b = blockIdx.x * 32 + b;
        int idx_b = __shfl_sync(0xffffffffu, idx, b);
        const float* ptr = pt + (size_t)idx_b * NC;
        const float* psr = ps + (size_t)s_b * NC;
        float acc = 0.0f;
        for (int c = lane; c < NC; c += 32) {  // 3 coalesced rounds
            float p = ptr[c];
            float q = psr[c];
            if (p > 0.0f) acc += p * (__logf(p) - __logf(q));
        }
#pragma unroll
        for (int o = 16; o > 0; o >>= 1)
            acc += __shfl_xor_sync(0xffffffffu, acc, o);
        a_sum += acc;                          // same value in every lane
    }

    // warp-reduce below/flag
#pragma unroll
    for (int o = 16; o > 0; o >>= 1) {
        b_val += __shfl_xor_sync(0xffffffffu, b_val, o);
        f_val += __shfl_xor_sync(0xffffffffu, f_val, o);
    }

    bool isLast = false;
    if (lane == 0) {
        g_bpart[blockIdx.x * 3 + 0] = a_sum;
        g_bpart[blockIdx.x * 3 + 1] = b_val;
        g_bpart[blockIdx.x * 3 + 2] = f_val;
        __threadfence();
        unsigned int old = atomicAdd(&g_count, 1u);
        isLast = (old == (unsigned)(gridDim.x - 1));
    }
    isLast = __shfl_sync(0xffffffffu, isLast, 0);

    if (isLast) {
        // fixed-order final reduction over 256 partials (deterministic)
        float a = 0.0f, b = 0.0f, f = 0.0f;
        for (int i = lane; i < ROW_BLOCKS; i += 32) {
            a += g_bpart[i * 3 + 0];
            b += g_bpart[i * 3 + 1];
            f += g_bpart[i * 3 + 2];
        }
#pragma unroll
        for (int o = 16; o > 0; o >>= 1) {
            a += __shfl_xor_sync(0xffffffffu, a, o);
            b += __shfl_xor_sync(0xffffffffu, b, o);
            f += __shfl_xor_sync(0xffffffffu, f, o);
        }
        if (lane == 0) {
            float na = f;
            float nb = (float)NS - na;
            float at = (na > 0.0f) ? a / (na * (float)NC) : 0.0f;
            float bt = (nb > 0.0f) ? b / (nb * (float)NC) : 0.0f;
            out[0] = at + bt;
            g_count = 0;                       // self-reset for graph replay
        }
    }
}

// ---------------- launcher ----------------
extern "C" void kernel_launch(void* const* d_in, const int* in_sizes, int n_in,
                              void* d_out, int out_size) {
    const float* boxes_student = (const float*)d_in[0];
    const float* boxes_teacher = (const float*)d_in[1];
    const float* pred_student  = (const float*)d_in[2];
    const float* pred_teacher  = (const float*)d_in[3];
    float* out = (float*)d_out;

    scan_kernel<<<2, 1024>>>(boxes_student, boxes_teacher);
    scatter_kernel<<<32, 256>>>(boxes_student, boxes_teacher, pred_student);

    dim3 gA(SBLK, TXB);    // 32 x 64 = 2048 blocks (proven shape)
    iou_kernel<<<gA, 256>>>();

    row_kernel<<<ROW_BLOCKS, 32>>>(pred_student, pred_teacher, out);
}

// round 14
// speedup vs baseline: 1.1405x; 1.1405x over previous
#include <cuda_runtime.h>
#include <math.h>

#define NS 8192
#define NT 8192
#define NC 91
#define NO_OBJ 90

#define SXB 32                  // student x bins
#define TXB 64                  // teacher x bins
#define YB  64                  // y bins (both)
#define NSCELL (SXB * YB)       // 2048
#define NTCELL (TXB * YB)       // 4096
#define SBLK (NS / 256)         // 32 student blocks of 256
#define ROW_BLOCKS (NS / 8)     // 1024 blocks, warp per student

// ---------------- scratch (static __device__, no allocations) ----------------
__device__ unsigned int g_cur[NSCELL + NTCELL];
__device__ int g_sstart[NSCELL + 1];
__device__ int g_tstart[NTCELL + 1];
__device__ float4 g_sbox[NS];          // sorted (x1,y1,x2+1,y2+1)
__device__ int    g_sidx[NS];
__device__ float4 g_tbox[NT];
__device__ float2 g_tmeta[NT];         // (area, idx_bits)
__device__ unsigned long long g_key[NS];   // per ORIGINAL student packed best
__device__ float g_bel[NS];            // precomputed -log ps[s][NO_OBJ]
__device__ float g_bpart[ROW_BLOCKS * 3];
__device__ unsigned int g_count = 0;

__device__ __forceinline__ int bin_sx(float x) {
    return min(max((int)(x * (SXB / 1000.0f)), 0), SXB - 1);
}
__device__ __forceinline__ int bin_tx(float x) {
    return min(max((int)(x * (TXB / 1000.0f)), 0), TXB - 1);
}
__device__ __forceinline__ int bin_y(float y) {
    return min(max((int)(y * (YB / 1000.0f)), 0), YB - 1);
}

__device__ __forceinline__ unsigned int wscan(unsigned int x, int lane) {
#pragma unroll
    for (int o = 1; o < 32; o <<= 1) {
        unsigned int y = __shfl_up_sync(0xffffffffu, x, o);
        if (lane >= o) x += y;
    }
    return x;
}

// Conservative integer prune, units of 1/32 px, +-1 slack for float-bin rounding.
__device__ __forceinline__ void block_xbounds(int sb, int& BXLO, int& BXHI) {
    int b0 = bin_sx(g_sbox[sb * 256].x);
    int b1 = bin_sx(g_sbox[sb * 256 + 255].x);
    BXLO = b0 * 1000 - 1;                  // 31.25px * 32 = 1000
    BXHI = (b1 + 1) * 1000 + 3361;         // + maxExtent 105px*32 + slack
}
__device__ __forceinline__ bool tx_live(int tx, int BXLO, int BXHI) {
    int TXLO = tx * 500 - 1;               // 15.625px * 32 = 500
    int TXHI = (tx + 1) * 500 + 3361;
    return !(TXLO >= BXHI || TXHI <= BXLO);
}

// ---------------- kernel 1: fused hist(smem)+scan (2 independent blocks) ----
__global__ void __launch_bounds__(1024) scan_kernel(const float* __restrict__ bs,
                                                    const float* __restrict__ bt) {
    __shared__ unsigned int ws[32];
    int tid = threadIdx.x, lane = tid & 31, w = tid >> 5;

    if (blockIdx.x == 0) {
        // ----- students: smem histogram + scan + g_key reset -----
        __shared__ unsigned int sh[NSCELL];
        sh[2 * tid] = 0; sh[2 * tid + 1] = 0;
#pragma unroll
        for (int k = 0; k < 8; k++) g_key[tid + k * 1024] = 0ull;  // replay reset
        __syncthreads();
#pragma unroll
        for (int k = 0; k < 8; k++) {
            float4 r = ((const float4*)bs)[tid + k * 1024];
            atomicAdd(&sh[bin_sx(r.x) * YB + bin_y(r.y)], 1u);
        }
        __syncthreads();
        unsigned int v0 = sh[2 * tid], v1 = sh[2 * tid + 1];
        unsigned int tot = v0 + v1;
        unsigned int x = wscan(tot, lane);
        if (lane == 31) ws[w] = x;
        __syncthreads();
        if (w == 0) { unsigned int a = ws[lane]; unsigned int sa = wscan(a, lane); ws[lane] = sa - a; }
        __syncthreads();
        unsigned int base = x - tot + ws[w];
        g_sstart[2 * tid] = (int)base;
        g_sstart[2 * tid + 1] = (int)(base + v0);
        g_cur[2 * tid] = base;
        g_cur[2 * tid + 1] = base + v0;
        if (tid == 0) g_sstart[NSCELL] = NS;
    } else {
        // ----- teachers: smem histogram + scan -----
        __shared__ unsigned int sh[NTCELL];
#pragma unroll
        for (int k = 0; k < 4; k++) sh[4 * tid + k] = 0;
        __syncthreads();
#pragma unroll
        for (int k = 0; k < 8; k++) {
            float4 r = ((const float4*)bt)[tid + k * 1024];
            atomicAdd(&sh[bin_tx(r.x) * YB + bin_y(r.y)], 1u);
        }
        __syncthreads();
        unsigned int v[4]; unsigned int tot = 0;
#pragma unroll
        for (int k = 0; k < 4; k++) { v[k] = sh[4 * tid + k]; tot += v[k]; }
        unsigned int x = wscan(tot, lane);
        if (lane == 31) ws[w] = x;
        __syncthreads();
        if (w == 0) { unsigned int a = ws[lane]; unsigned int sa = wscan(a, lane); ws[lane] = sa - a; }
        __syncthreads();
        unsigned int base = x - tot + ws[w];
#pragma unroll
        for (int k = 0; k < 4; k++) {
            g_tstart[4 * tid + k] = (int)base;
            g_cur[NSCELL + 4 * tid + k] = base;
            base += v[k];
        }
        if (tid == 0) g_tstart[NTCELL] = NT;
    }
}

// ---------------- kernel 2: scatter + precompute below-term ----------------
__global__ void __launch_bounds__(256) scatter_kernel(const float* __restrict__ bs,
                                                      const float* __restrict__ bt,
                                                      const float* __restrict__ ps) {
    int i = blockIdx.x * 256 + threadIdx.x;
    g_bel[i] = -__logf(ps[(size_t)i * NC + NO_OBJ]);   // hides under atomic latency
    {
        float4 r = ((const float4*)bs)[i];
        unsigned int pos = atomicAdd(&g_cur[bin_sx(r.x) * YB + bin_y(r.y)], 1u);
        g_sbox[pos] = make_float4(r.x, r.y, r.z + 1.0f, r.w + 1.0f);
        g_sidx[pos] = i;
    }
    {
        float4 r = ((const float4*)bt)[i];
        unsigned int pos = atomicAdd(&g_cur[NSCELL + bin_tx(r.x) * YB + bin_y(r.y)], 1u);
        float x2 = r.z + 1.0f, y2 = r.w + 1.0f;
        g_tbox[pos] = make_float4(r.x, r.y, x2, y2);
        g_tmeta[pos] = make_float2((x2 - r.x) * (y2 - r.y), __int_as_float(i));
    }
}

#define IOU_STEP(J, U, D, I) {                                        \
    float4 t = __ldg(&g_tbox[J]); float2 m = __ldg(&g_tmeta[J]);      \
    float w_ = fminf(sbx.z, t.z) - fmaxf(sbx.x, t.x);                 \
    float h_ = fminf(sbx.w, t.w) - fmaxf(sbx.y, t.y);                 \
    w_ = fmaxf(w_, 0.0f);          /* h unclamped: u<=0 never wins */ \
    float u_ = w_ * h_;                                               \
    float dd_ = sA + m.x;                                             \
    if (u_ * (D) > (U) * dd_) { U = u_; D = dd_; I = __float_as_int(m.y); } }

#define CHAIN_MERGE(UB, DB, IB, UO, DO_, IO) {                        \
    float l_ = (UO) * (DB), r_ = (UB) * (DO_);                        \
    if (l_ > r_ || (l_ == r_ && (IO) < (IB))) { UB = UO; DB = DO_; IB = IO; } }

// ---------------- kernel 3: pruned, y-windowed IoU argmax -> atomicMax ------
__global__ void __launch_bounds__(256) iou_kernel() {
    int tid = threadIdx.x;
    int sb = blockIdx.x, tx = blockIdx.y;

    int BXLO, BXHI;
    block_xbounds(sb, BXLO, BXHI);
    if (!tx_live(tx, BXLO, BXHI)) return;     // block-uniform early exit, ~10 instr

    int p = sb * 256 + tid;
    float4 sbx = g_sbox[p];
    float sA = (sbx.z - sbx.x) * (sbx.w - sbx.y);

    // warp y-window (students y-sorted within block -> tight per warp)
    float wy0 = sbx.y, wy1 = sbx.w;
#pragma unroll
    for (int o = 16; o > 0; o >>= 1) {
        wy0 = fminf(wy0, __shfl_xor_sync(0xffffffffu, wy0, o));
        wy1 = fmaxf(wy1, __shfl_xor_sync(0xffffffffu, wy1, o));
    }
    int ylo = bin_y(wy0 - 105.0f);
    int yhi = bin_y(wy1);
    int jlo = g_tstart[(tx << 6) + ylo];       // exact contiguous window from
    int jhi = g_tstart[(tx << 6) + yhi + 1];   // bin table (order-independent)

    float u0 = 0.0f, d0 = 1.0f; int i0 = 0x7fffffff;
    float u1 = 0.0f, d1 = 1.0f; int i1 = 0x7fffffff;
    float u2 = 0.0f, d2 = 1.0f; int i2 = 0x7fffffff;
    float u3 = 0.0f, d3 = 1.0f; int i3 = 0x7fffffff;

    // warp-uniform addresses -> broadcast LDG; 4 chains hide load+select latency
    int j = jlo;
    for (; j + 3 < jhi; j += 4) {
        IOU_STEP(j,     u0, d0, i0);
        IOU_STEP(j + 1, u1, d1, i1);
        IOU_STEP(j + 2, u2, d2, i2);
        IOU_STEP(j + 3, u3, d3, i3);
    }
    for (; j < jhi; j++) IOU_STEP(j, u0, d0, i0);

    CHAIN_MERGE(u0, d0, i0, u1, d1, i1);
    CHAIN_MERGE(u2, d2, i2, u3, d3, i3);
    CHAIN_MERGE(u0, d0, i0, u2, d2, i2);

    if (u0 > 0.0f) {
        // ratio = u/d in [0, 0.5]; bits monotone. Low word: larger = smaller idx.
        float ratio = u0 / d0;
        unsigned long long key =
            ((unsigned long long)__float_as_uint(ratio) << 32) |
            (unsigned int)(0x7fffffff - i0);
        atomicMax(&g_key[g_sidx[p]], key);     // order-independent -> deterministic
    }
}

// ---------------- kernel 4: warp-per-student row loss + final reduce --------
__global__ void __launch_bounds__(256) row_kernel(const float* __restrict__ ps,
                                                  const float* __restrict__ pt,
                                                  float* __restrict__ out) {
    __shared__ float s_a[8], s_b[8], s_f[8];
    __shared__ bool  isLast;

    int tid  = threadIdx.x;
    int wid  = tid >> 5;
    int lane = tid & 31;
    int s = blockIdx.x * 8 + wid;          // ORIGINAL student id

    unsigned long long key = g_key[s];     // broadcast load
    float ratio = __uint_as_float((unsigned int)(key >> 32));
    int idx = 0x7fffffff - (int)(key & 0xffffffffu);

    float iou = ratio / (1.0f - ratio);    // == u/(d-u), well-conditioned (ratio<=0.5)
    bool above = iou > 0.75f;

    float a_val = 0.0f, b_val = 0.0f, f_val = 0.0f;
    if (above) {
        const float* ptr = pt + (size_t)idx * NC;
        const float* psr = ps + (size_t)s * NC;
        float acc = 0.0f;
        for (int c = lane; c < NC; c += 32) {
            float p = ptr[c];
            float q = psr[c];
            if (p > 0.0f) acc += p * (__logf(p) - __logf(q));
        }
#pragma unroll
        for (int o = 16; o > 0; o >>= 1)
            acc += __shfl_xor_sync(0xffffffffu, acc, o);
        a_val = acc;
        f_val = 1.0f;
    } else {
        if (lane == 0) b_val = g_bel[s];   // precomputed; no ps gather, no MUFU
    }

    if (lane == 0) { s_a[wid] = a_val; s_b[wid] = b_val; s_f[wid] = f_val; }
    __syncthreads();

    if (tid == 0) {
        float a = 0.0f, b = 0.0f, f = 0.0f;
#pragma unroll
        for (int w = 0; w < 8; w++) { a += s_a[w]; b += s_b[w]; f += s_f[w]; }
        g_bpart[blockIdx.x * 3 + 0] = a;
        g_bpart[blockIdx.x * 3 + 1] = b;
        g_bpart[blockIdx.x * 3 + 2] = f;
        __threadfence();
        unsigned int old = atomicAdd(&g_count, 1u);
        isLast = (old == (unsigned)(gridDim.x - 1));
    }
    __syncthreads();

    if (isLast) {
        __shared__ float ra[256], rb[256], rf[256];
        float a = 0.0f, b = 0.0f, f = 0.0f;
        for (int i = tid; i < ROW_BLOCKS; i += 256) {
            a += g_bpart[i * 3 + 0];
            b += g_bpart[i * 3 + 1];
            f += g_bpart[i * 3 + 2];
        }
        ra[tid] = a; rb[tid] = b; rf[tid] = f;
        __syncthreads();
        for (int o = 128; o > 0; o >>= 1) {
            if (tid < o) {
                ra[tid] += ra[tid + o];
                rb[tid] += rb[tid + o];
                rf[tid] += rf[tid + o];
            }
            __syncthreads();
        }
        if (tid == 0) {
            float na = rf[0];
            float nb = (float)NS - na;
            float at = (na > 0.0f) ? ra[0] / (na * (float)NC) : 0.0f;
            float bt = (nb > 0.0f) ? rb[0] / (nb * (float)NC) : 0.0f;
            out[0] = at + bt;
            g_count = 0;                   // self-reset for graph replay
        }
    }
}

// ---------------- launcher ----------------
extern "C" void kernel_launch(void* const* d_in, const int* in_sizes, int n_in,
                              void* d_out, int out_size) {
    const float* boxes_student = (const float*)d_in[0];
    const float* boxes_teacher = (const float*)d_in[1];
    const float* pred_student  = (const float*)d_in[2];
    const float* pred_teacher  = (const float*)d_in[3];
    float* out = (float*)d_out;

    scan_kernel<<<2, 1024>>>(boxes_student, boxes_teacher);
    scatter_kernel<<<32, 256>>>(boxes_student, boxes_teacher, pred_student);

    dim3 gA(SBLK, TXB);    // 32 x 64 = 2048 blocks (proven shape)
    iou_kernel<<<gA, 256>>>();

    row_kernel<<<ROW_BLOCKS, 256>>>(pred_student, pred_teacher, out);
}

// round 15
// speedup vs baseline: 1.1681x; 1.0242x over previous
#include <cuda_runtime.h>
#include <math.h>

#define NS 8192
#define NT 8192
#define NC 91
#define NO_OBJ 90

#define SXB 32                  // student x bins
#define TXB 64                  // teacher x bins
#define YB  64                  // y bins (both)
#define NSCELL (SXB * YB)       // 2048
#define NTCELL (TXB * YB)       // 4096
#define SBLK (NS / 256)         // 32 student blocks of 256
#define ROW_BLOCKS (NS / 8)     // 1024 blocks, warp per student

// ---------------- scratch (static __device__, no allocations) ----------------
__device__ unsigned int g_cur[NSCELL + NTCELL];
__device__ int g_sstart[NSCELL + 1];
__device__ int g_tstart[NTCELL + 1];
__device__ float4 g_sbox[NS];          // sorted (x1,y1,x2+1,y2+1)
__device__ int    g_sidx[NS];
__device__ float4 g_tbox[NT];
__device__ float2 g_tmeta[NT];         // (area, idx_bits)
__device__ unsigned long long g_key[NS];   // per ORIGINAL student packed best
__device__ float g_bel[NS];            // precomputed -log ps[s][NO_OBJ]
// fixed-point accumulators (2^32 scale); integer adds commute -> deterministic
__device__ unsigned long long g_accA = 0ull;   // above KL sum
__device__ unsigned long long g_accB = 0ull;   // below sum
__device__ unsigned long long g_accN = 0ull;   // above count (integer)

__device__ __forceinline__ int bin_sx(float x) {
    return min(max((int)(x * (SXB / 1000.0f)), 0), SXB - 1);
}
__device__ __forceinline__ int bin_tx(float x) {
    return min(max((int)(x * (TXB / 1000.0f)), 0), TXB - 1);
}
__device__ __forceinline__ int bin_y(float y) {
    return min(max((int)(y * (YB / 1000.0f)), 0), YB - 1);
}

__device__ __forceinline__ unsigned int wscan(unsigned int x, int lane) {
#pragma unroll
    for (int o = 1; o < 32; o <<= 1) {
        unsigned int y = __shfl_up_sync(0xffffffffu, x, o);
        if (lane >= o) x += y;
    }
    return x;
}

// Conservative integer prune, units of 1/32 px, +-1 slack for float-bin rounding.
__device__ __forceinline__ void block_xbounds(int sb, int& BXLO, int& BXHI) {
    int b0 = bin_sx(g_sbox[sb * 256].x);
    int b1 = bin_sx(g_sbox[sb * 256 + 255].x);
    BXLO = b0 * 1000 - 1;                  // 31.25px * 32 = 1000
    BXHI = (b1 + 1) * 1000 + 3361;         // + maxExtent 105px*32 + slack
}
__device__ __forceinline__ bool tx_live(int tx, int BXLO, int BXHI) {
    int TXLO = tx * 500 - 1;               // 15.625px * 32 = 500
    int TXHI = (tx + 1) * 500 + 3361;
    return !(TXLO >= BXHI || TXHI <= BXLO);
}

// ---------------- kernel 1: fused hist(smem)+scan (2 independent blocks) ----
__global__ void __launch_bounds__(1024) scan_kernel(const float* __restrict__ bs,
                                                    const float* __restrict__ bt) {
    __shared__ unsigned int ws[32];
    int tid = threadIdx.x, lane = tid & 31, w = tid >> 5;

    if (blockIdx.x == 0) {
        // ----- students: smem histogram + scan + g_key reset -----
        __shared__ unsigned int sh[NSCELL];
        sh[2 * tid] = 0; sh[2 * tid + 1] = 0;
#pragma unroll
        for (int k = 0; k < 8; k++) g_key[tid + k * 1024] = 0ull;  // replay reset
        __syncthreads();
#pragma unroll
        for (int k = 0; k < 8; k++) {
            float4 r = ((const float4*)bs)[tid + k * 1024];
            atomicAdd(&sh[bin_sx(r.x) * YB + bin_y(r.y)], 1u);
        }
        __syncthreads();
        unsigned int v0 = sh[2 * tid], v1 = sh[2 * tid + 1];
        unsigned int tot = v0 + v1;
        unsigned int x = wscan(tot, lane);
        if (lane == 31) ws[w] = x;
        __syncthreads();
        if (w == 0) { unsigned int a = ws[lane]; unsigned int sa = wscan(a, lane); ws[lane] = sa - a; }
        __syncthreads();
        unsigned int base = x - tot + ws[w];
        g_sstart[2 * tid] = (int)base;
        g_sstart[2 * tid + 1] = (int)(base + v0);
        g_cur[2 * tid] = base;
        g_cur[2 * tid + 1] = base + v0;
        if (tid == 0) g_sstart[NSCELL] = NS;
    } else {
        // ----- teachers: smem histogram + scan -----
        __shared__ unsigned int sh[NTCELL];
#pragma unroll
        for (int k = 0; k < 4; k++) sh[4 * tid + k] = 0;
        __syncthreads();
#pragma unroll
        for (int k = 0; k < 8; k++) {
            float4 r = ((const float4*)bt)[tid + k * 1024];
            atomicAdd(&sh[bin_tx(r.x) * YB + bin_y(r.y)], 1u);
        }
        __syncthreads();
        unsigned int v[4]; unsigned int tot = 0;
#pragma unroll
        for (int k = 0; k < 4; k++) { v[k] = sh[4 * tid + k]; tot += v[k]; }
        unsigned int x = wscan(tot, lane);
        if (lane == 31) ws[w] = x;
        __syncthreads();
        if (w == 0) { unsigned int a = ws[lane]; unsigned int sa = wscan(a, lane); ws[lane] = sa - a; }
        __syncthreads();
        unsigned int base = x - tot + ws[w];
#pragma unroll
        for (int k = 0; k < 4; k++) {
            g_tstart[4 * tid + k] = (int)base;
            g_cur[NSCELL + 4 * tid + k] = base;
            base += v[k];
        }
        if (tid == 0) g_tstart[NTCELL] = NT;
    }
}

// ---------------- kernel 2: scatter + precompute below-term ----------------
__global__ void __launch_bounds__(256) scatter_kernel(const float* __restrict__ bs,
                                                      const float* __restrict__ bt,
                                                      const float* __restrict__ ps) {
    int i = blockIdx.x * 256 + threadIdx.x;
    g_bel[i] = -__logf(ps[(size_t)i * NC + NO_OBJ]);   // hides under atomic latency
    {
        float4 r = ((const float4*)bs)[i];
        unsigned int pos = atomicAdd(&g_cur[bin_sx(r.x) * YB + bin_y(r.y)], 1u);
        g_sbox[pos] = make_float4(r.x, r.y, r.z + 1.0f, r.w + 1.0f);
        g_sidx[pos] = i;
    }
    {
        float4 r = ((const float4*)bt)[i];
        unsigned int pos = atomicAdd(&g_cur[NSCELL + bin_tx(r.x) * YB + bin_y(r.y)], 1u);
        float x2 = r.z + 1.0f, y2 = r.w + 1.0f;
        g_tbox[pos] = make_float4(r.x, r.y, x2, y2);
        g_tmeta[pos] = make_float2((x2 - r.x) * (y2 - r.y), __int_as_float(i));
    }
}

#define IOU_STEP(J, U, D, I) {                                        \
    float4 t = __ldg(&g_tbox[J]); float2 m = __ldg(&g_tmeta[J]);      \
    float w_ = fminf(sbx.z, t.z) - fmaxf(sbx.x, t.x);                 \
    float h_ = fminf(sbx.w, t.w) - fmaxf(sbx.y, t.y);                 \
    w_ = fmaxf(w_, 0.0f);          /* h unclamped: u<=0 never wins */ \
    float u_ = w_ * h_;                                               \
    float dd_ = sA + m.x;                                             \
    if (u_ * (D) > (U) * dd_) { U = u_; D = dd_; I = __float_as_int(m.y); } }

#define CHAIN_MERGE(UB, DB, IB, UO, DO_, IO) {                        \
    float l_ = (UO) * (DB), r_ = (UB) * (DO_);                        \
    if (l_ > r_ || (l_ == r_ && (IO) < (IB))) { UB = UO; DB = DO_; IB = IO; } }

// ---------------- kernel 3: pruned, y-windowed IoU argmax -> atomicMax ------
__global__ void __launch_bounds__(256) iou_kernel() {
    int tid = threadIdx.x;
    int sb = blockIdx.x, tx = blockIdx.y;

    int BXLO, BXHI;
    block_xbounds(sb, BXLO, BXHI);
    if (!tx_live(tx, BXLO, BXHI)) return;     // block-uniform early exit, ~10 instr

    int p = sb * 256 + tid;
    float4 sbx = g_sbox[p];
    float sA = (sbx.z - sbx.x) * (sbx.w - sbx.y);

    // warp y-window (students y-sorted within block -> tight per warp)
    float wy0 = sbx.y, wy1 = sbx.w;
#pragma unroll
    for (int o = 16; o > 0; o >>= 1) {
        wy0 = fminf(wy0, __shfl_xor_sync(0xffffffffu, wy0, o));
        wy1 = fmaxf(wy1, __shfl_xor_sync(0xffffffffu, wy1, o));
    }
    int ylo = bin_y(wy0 - 105.0f);
    int yhi = bin_y(wy1);
    int jlo = g_tstart[(tx << 6) + ylo];       // exact contiguous window from
    int jhi = g_tstart[(tx << 6) + yhi + 1];   // bin table (order-independent)

    float u0 = 0.0f, d0 = 1.0f; int i0 = 0x7fffffff;
    float u1 = 0.0f, d1 = 1.0f; int i1 = 0x7fffffff;
    float u2 = 0.0f, d2 = 1.0f; int i2 = 0x7fffffff;
    float u3 = 0.0f, d3 = 1.0f; int i3 = 0x7fffffff;

    // warp-uniform addresses -> broadcast LDG; 4 chains hide load+select latency
    int j = jlo;
    for (; j + 3 < jhi; j += 4) {
        IOU_STEP(j,     u0, d0, i0);
        IOU_STEP(j + 1, u1, d1, i1);
        IOU_STEP(j + 2, u2, d2, i2);
        IOU_STEP(j + 3, u3, d3, i3);
    }
    for (; j < jhi; j++) IOU_STEP(j, u0, d0, i0);

    CHAIN_MERGE(u0, d0, i0, u1, d1, i1);
    CHAIN_MERGE(u2, d2, i2, u3, d3, i3);
    CHAIN_MERGE(u0, d0, i0, u2, d2, i2);

    if (u0 > 0.0f) {
        // ratio = u/d in [0, 0.5]; bits monotone. Low word: larger = smaller idx.
        float ratio = u0 / d0;
        unsigned long long key =
            ((unsigned long long)__float_as_uint(ratio) << 32) |
            (unsigned int)(0x7fffffff - i0);
        atomicMax(&g_key[g_sidx[p]], key);     // order-independent -> deterministic
    }
}

// ---------------- kernel 4: warp-per-student row loss, fence-free retire ----
__global__ void __launch_bounds__(256) row_kernel(const float* __restrict__ ps,
                                                  const float* __restrict__ pt) {
    __shared__ float s_a[8], s_b[8], s_f[8];

    int tid  = threadIdx.x;
    int wid  = tid >> 5;
    int lane = tid & 31;
    int s = blockIdx.x * 8 + wid;          // ORIGINAL student id

    unsigned long long key = g_key[s];     // broadcast load
    float ratio = __uint_as_float((unsigned int)(key >> 32));
    int idx = 0x7fffffff - (int)(key & 0xffffffffu);

    float iou = ratio / (1.0f - ratio);    // == u/(d-u), well-conditioned (ratio<=0.5)
    bool above = iou > 0.75f;

    float a_val = 0.0f, b_val = 0.0f, f_val = 0.0f;
    if (above) {
        const float* ptr = pt + (size_t)idx * NC;
        const float* psr = ps + (size_t)s * NC;
        float acc = 0.0f;
        for (int c = lane; c < NC; c += 32) {
            float p = ptr[c];
            float q = psr[c];
            if (p > 0.0f) acc += p * (__logf(p) - __logf(q));
        }
#pragma unroll
        for (int o = 16; o > 0; o >>= 1)
            acc += __shfl_xor_sync(0xffffffffu, acc, o);
        a_val = acc;
        f_val = 1.0f;
    } else {
        if (lane == 0) b_val = g_bel[s];   // precomputed
    }

    if (lane == 0) { s_a[wid] = a_val; s_b[wid] = b_val; s_f[wid] = f_val; }
    __syncthreads();

    if (tid == 0) {
        float a = 0.0f, b = 0.0f, f = 0.0f;
#pragma unroll
        for (int w = 0; w < 8; w++) { a += s_a[w]; b += s_b[w]; f += s_f[w]; }
        // fixed-point (2^32) integer adds: exact commutativity -> deterministic.
        // No fence, no retirement counter, no tail reduction.
        if (a > 0.0f) atomicAdd(&g_accA, (unsigned long long)((double)a * 4294967296.0 + 0.5));
        if (b > 0.0f) atomicAdd(&g_accB, (unsigned long long)((double)b * 4294967296.0 + 0.5));
        if (f > 0.0f) atomicAdd(&g_accN, (unsigned long long)f);
    }
}

// ---------------- kernel 5: trivial finish + accumulator reset --------------
__global__ void finish_kernel(float* __restrict__ out) {
    if (threadIdx.x == 0) {
        double a = (double)g_accA * (1.0 / 4294967296.0);
        double b = (double)g_accB * (1.0 / 4294967296.0);
        double na = (double)g_accN;
        double nb = (double)NS - na;
        float at = (na > 0.0) ? (float)(a / (na * (double)NC)) : 0.0f;
        float bt = (nb > 0.0) ? (float)(b / (nb * (double)NC)) : 0.0f;
        out[0] = at + bt;
        g_accA = 0ull; g_accB = 0ull; g_accN = 0ull;   // replay reset
    }
}

// ---------------- launcher ----------------
extern "C" void kernel_launch(void* const* d_in, const int* in_sizes, int n_in,
                              void* d_out, int out_size) {
    const float* boxes_student = (const float*)d_in[0];
    const float* boxes_teacher = (const float*)d_in[1];
    const float* pred_student  = (const float*)d_in[2];
    const float* pred_teacher  = (const float*)d_in[3];
    float* out = (float*)d_out;

    scan_kernel<<<2, 1024>>>(boxes_student, boxes_teacher);
    scatter_kernel<<<32, 256>>>(boxes_student, boxes_teacher, pred_student);

    dim3 gA(SBLK, TXB);    // 32 x 64 = 2048 blocks (proven shape)
    iou_kernel<<<gA, 256>>>();

    row_kernel<<<ROW_BLOCKS, 256>>>(pred_student, pred_teacher);
    finish_kernel<<<1, 32>>>(out);
}